// round 1
// baseline (speedup 1.0000x reference)
#include <cuda_runtime.h>
#include <cstdint>

// AutoInt: 3 layers of per-batch self-attention on [8192, 64, 64] fp32.
//   S = X X^T ; A = softmax_rows(S) ; X = A X   (x3), out = X flattened.
// One CTA per batch; everything resident in SMEM; packed f32x2 FMAs.

#define NDIM   64
#define PITCH  68          // 64 + 4 floats padding (bank-conflict control)
#define LAYERS 3

// ---- packed f32x2 helpers (PTX-only; ptxas never auto-fuses these) ----
__device__ __forceinline__ unsigned long long fma2(unsigned long long a,
                                                   unsigned long long b,
                                                   unsigned long long c) {
    unsigned long long d;
    asm("fma.rn.f32x2 %0, %1, %2, %3;" : "=l"(d) : "l"(a), "l"(b), "l"(c));
    return d;
}
__device__ __forceinline__ unsigned long long dup2(float x) {
    unsigned long long d;
    asm("mov.b64 %0, {%1, %1};" : "=l"(d) : "f"(x));
    return d;
}
__device__ __forceinline__ float2 unpack2(unsigned long long v) {
    float lo, hi;
    asm("mov.b64 {%0, %1}, %2;" : "=f"(lo), "=f"(hi) : "l"(v));
    return make_float2(lo, hi);
}

__global__ __launch_bounds__(256)
void autoint_kernel(const float* __restrict__ in, float* __restrict__ out) {
    __shared__ float X[NDIM * PITCH];
    __shared__ float S[NDIM * PITCH];

    const int tid  = threadIdx.x;       // 256 threads
    const int tx   = tid & 15;          // 16 x 16 thread grid
    const int ty   = tid >> 4;
    const int lane = tid & 31;
    const int warp = tid >> 5;          // 8 warps
    const size_t base = (size_t)blockIdx.x * (NDIM * NDIM);

    // ---- load batch tile [64,64] -> SMEM (float4, coalesced) ----
    {
        const float4* src = (const float4*)(in + base);
        #pragma unroll
        for (int i = 0; i < 4; i++) {
            int idx = tid + i * 256;            // 1024 float4 total
            float4 v = src[idx];
            int r = idx >> 4, c = (idx & 15) << 2;
            *(float4*)&X[r * PITCH + c] = v;
        }
    }
    __syncthreads();

    for (int layer = 0; layer < LAYERS; layer++) {
        // ================= GEMM1: S = X X^T =================
        // thread tile: rows i = ty+16r, cols j = tx+16s (strided tiles ->
        // per-phase distinct bank-groups on the 16 B-row LDS.128s).
        // k is contiguous for BOTH operands -> ulonglong2 loads give packed
        // f32 pairs for fma.rn.f32x2 with zero pack instructions.
        {
            unsigned long long acc[4][4];
            #pragma unroll
            for (int r = 0; r < 4; r++)
                #pragma unroll
                for (int s = 0; s < 4; s++) acc[r][s] = 0ull;

            #pragma unroll 4
            for (int k = 0; k < NDIM; k += 4) {
                ulonglong2 av[4], bv[4];
                #pragma unroll
                for (int r = 0; r < 4; r++)
                    av[r] = *(const ulonglong2*)&X[(ty + 16 * r) * PITCH + k];
                #pragma unroll
                for (int s = 0; s < 4; s++)
                    bv[s] = *(const ulonglong2*)&X[(tx + 16 * s) * PITCH + k];
                #pragma unroll
                for (int r = 0; r < 4; r++)
                    #pragma unroll
                    for (int s = 0; s < 4; s++) {
                        acc[r][s] = fma2(av[r].x, bv[s].x, acc[r][s]);
                        acc[r][s] = fma2(av[r].y, bv[s].y, acc[r][s]);
                    }
            }
            #pragma unroll
            for (int r = 0; r < 4; r++)
                #pragma unroll
                for (int s = 0; s < 4; s++) {
                    float2 f = unpack2(acc[r][s]);
                    S[(ty + 16 * r) * PITCH + (tx + 16 * s)] = f.x + f.y;
                }
        }
        __syncthreads();

        // ================= softmax over rows of S =================
        // warp w owns rows 8w..8w+7; each lane covers 2 elements.
        #pragma unroll
        for (int rr = 0; rr < 8; rr++) {
            int row = warp * 8 + rr;
            float v0 = S[row * PITCH + lane];
            float v1 = S[row * PITCH + lane + 32];
            float m = fmaxf(v0, v1);
            #pragma unroll
            for (int o = 16; o > 0; o >>= 1)
                m = fmaxf(m, __shfl_xor_sync(0xffffffffu, m, o));
            float e0 = __expf(v0 - m);
            float e1 = __expf(v1 - m);
            float sm = e0 + e1;
            #pragma unroll
            for (int o = 16; o > 0; o >>= 1)
                sm += __shfl_xor_sync(0xffffffffu, sm, o);
            float inv = __fdividef(1.0f, sm);
            S[row * PITCH + lane]      = e0 * inv;
            S[row * PITCH + lane + 32] = e1 * inv;
        }
        __syncthreads();

        // ================= GEMM2: X = A X   (A = S) =================
        // thread tile: rows i = ty+16r; col pairs (2tx, 2tx+1) and
        // (2tx+32, 2tx+33). X-column loads are LDS.64 spanning all 32
        // banks exactly once -> conflict-free. A scalar is dup2'd (ALU pipe).
        {
            unsigned long long acc2[4][2];
            #pragma unroll
            for (int r = 0; r < 4; r++) { acc2[r][0] = 0ull; acc2[r][1] = 0ull; }

            #pragma unroll 4
            for (int j = 0; j < NDIM; j += 2) {
                float2 a01[4];
                #pragma unroll
                for (int r = 0; r < 4; r++)
                    a01[r] = *(const float2*)&S[(ty + 16 * r) * PITCH + j];
                unsigned long long b0a = *(const unsigned long long*)&X[j * PITCH + 2 * tx];
                unsigned long long b0b = *(const unsigned long long*)&X[j * PITCH + 2 * tx + 32];
                unsigned long long b1a = *(const unsigned long long*)&X[(j + 1) * PITCH + 2 * tx];
                unsigned long long b1b = *(const unsigned long long*)&X[(j + 1) * PITCH + 2 * tx + 32];
                #pragma unroll
                for (int r = 0; r < 4; r++) {
                    unsigned long long d0 = dup2(a01[r].x);
                    unsigned long long d1 = dup2(a01[r].y);
                    acc2[r][0] = fma2(d0, b0a, acc2[r][0]);
                    acc2[r][1] = fma2(d0, b0b, acc2[r][1]);
                    acc2[r][0] = fma2(d1, b1a, acc2[r][0]);
                    acc2[r][1] = fma2(d1, b1b, acc2[r][1]);
                }
            }
            __syncthreads();   // all reads of old X finished before overwrite
            #pragma unroll
            for (int r = 0; r < 4; r++) {
                float2 f0 = unpack2(acc2[r][0]);
                float2 f1 = unpack2(acc2[r][1]);
                *(float2*)&X[(ty + 16 * r) * PITCH + 2 * tx]      = f0;
                *(float2*)&X[(ty + 16 * r) * PITCH + 2 * tx + 32] = f1;
            }
        }
        __syncthreads();
    }

    // ---- store [64,64] -> out[b, 4096] (float4, coalesced) ----
    {
        float4* dst = (float4*)(out + base);
        #pragma unroll
        for (int i = 0; i < 4; i++) {
            int idx = tid + i * 256;
            int r = idx >> 4, c = (idx & 15) << 2;
            dst[idx] = *(float4*)&X[r * PITCH + c];
        }
    }
}

extern "C" void kernel_launch(void* const* d_in, const int* in_sizes, int n_in,
                              void* d_out, int out_size) {
    const float* embeds = (const float*)d_in[0];
    float* out = (float*)d_out;
    int batches = in_sizes[0] / (NDIM * NDIM);   // 8192
    autoint_kernel<<<batches, 256>>>(embeds, out);
}

// round 2
// speedup vs baseline: 1.1494x; 1.1494x over previous
#include <cuda_runtime.h>
#include <cstdint>

// AutoInt [8192,64,64] fp32: 3 x { S = X X^T ; A = softmax(S) ; X = A X }.
// One CTA per batch. Tensor-pipe GEMMs: mma.sync.m16n8k8 tf32 with 3xTF32
// compensation (hi*hi + hi*lo + lo*hi) to stay within rel_err < 1e-3.

#define NDIM   64
#define P      68            // pitch: P mod 32 == 4 -> conflict-free mma frag loads
#define ASZ    (NDIM * P)    // floats per smem array
#define LAYERS 3
#define SMEM_BYTES (4 * ASZ * sizeof(float))

__device__ __forceinline__ float tf32r(float x) {
    uint32_t u;
    asm("cvt.rna.tf32.f32 %0, %1;" : "=r"(u) : "f"(x));
    return __uint_as_float(u);
}

__device__ __forceinline__ void mma_tf32(float d[4], const uint32_t a[4],
                                         const uint32_t b[2], const float c[4]) {
    asm("mma.sync.aligned.m16n8k8.row.col.f32.tf32.tf32.f32 "
        "{%0,%1,%2,%3}, {%4,%5,%6,%7}, {%8,%9}, {%10,%11,%12,%13};"
        : "=f"(d[0]), "=f"(d[1]), "=f"(d[2]), "=f"(d[3])
        : "r"(a[0]), "r"(a[1]), "r"(a[2]), "r"(a[3]),
          "r"(b[0]), "r"(b[1]),
          "f"(c[0]), "f"(c[1]), "f"(c[2]), "f"(c[3]));
}

// A fragment (m16k8, row-major): rows rbase+gid, rbase+gid+8; cols kk+tig, +4.
__device__ __forceinline__ void load_a(const float* __restrict__ arr, uint32_t f[4],
                                       int rbase, int kk, int gid, int tig) {
    f[0] = __float_as_uint(arr[(rbase + gid)     * P + kk + tig]);
    f[1] = __float_as_uint(arr[(rbase + gid + 8) * P + kk + tig]);
    f[2] = __float_as_uint(arr[(rbase + gid)     * P + kk + tig + 4]);
    f[3] = __float_as_uint(arr[(rbase + gid + 8) * P + kk + tig + 4]);
}

__global__ __launch_bounds__(256)
void autoint_tc_kernel(const float* __restrict__ in, float* __restrict__ out) {
    extern __shared__ float smem[];
    float* Xhi = smem;              // tf32-rounded X
    float* Xlo = smem + ASZ;        // tf32(X - Xhi)
    float* S   = smem + 2 * ASZ;    // scores, then Ahi in place
    float* Alo = smem + 3 * ASZ;    // tf32 residual of attention weights

    const int tid  = threadIdx.x;          // 256 threads, 8 warps
    const int lane = tid & 31;
    const int warp = tid >> 5;
    const int gid  = lane >> 2;            // 0..7
    const int tig  = lane & 3;             // 0..3
    const int mb   = (warp >> 1) * 16;     // warp's row block
    const int nb0  = (warp & 1) * 32;      // warp's col half (4 n-tiles of 8)
    const size_t base = (size_t)blockIdx.x * (NDIM * NDIM);

    // ---- load + split: gmem -> Xhi/Xlo ----
    {
        const float4* src = (const float4*)(in + base);
        #pragma unroll
        for (int i = 0; i < 4; i++) {
            int idx = tid + i * 256;                 // 1024 float4
            float4 v = src[idx];
            int r = idx >> 4, c = (idx & 15) << 2;
            float4 h, l;
            h.x = tf32r(v.x); l.x = tf32r(v.x - h.x);
            h.y = tf32r(v.y); l.y = tf32r(v.y - h.y);
            h.z = tf32r(v.z); l.z = tf32r(v.z - h.z);
            h.w = tf32r(v.w); l.w = tf32r(v.w - h.w);
            *(float4*)&Xhi[r * P + c] = h;
            *(float4*)&Xlo[r * P + c] = l;
        }
    }
    __syncthreads();

    for (int layer = 0; layer < LAYERS; layer++) {
        // ============ GEMM1: S = X X^T (3xTF32) ============
        {
            float acc[4][4];
            #pragma unroll
            for (int t = 0; t < 4; t++)
                #pragma unroll
                for (int i = 0; i < 4; i++) acc[t][i] = 0.0f;

            #pragma unroll
            for (int k = 0; k < NDIM; k += 8) {
                uint32_t ah[4], al[4];
                load_a(Xhi, ah, mb, k, gid, tig);
                load_a(Xlo, al, mb, k, gid, tig);
                #pragma unroll
                for (int t = 0; t < 4; t++) {
                    int nb = nb0 + t * 8;
                    // B = X^T: B[k][n] = X[n][k]; b0:(k=tig,n=gid) b1:(k=tig+4)
                    uint32_t bh[2], bl[2];
                    bh[0] = __float_as_uint(Xhi[(nb + gid) * P + k + tig]);
                    bh[1] = __float_as_uint(Xhi[(nb + gid) * P + k + tig + 4]);
                    bl[0] = __float_as_uint(Xlo[(nb + gid) * P + k + tig]);
                    bl[1] = __float_as_uint(Xlo[(nb + gid) * P + k + tig + 4]);
                    mma_tf32(acc[t], ah, bh, acc[t]);
                    mma_tf32(acc[t], ah, bl, acc[t]);
                    mma_tf32(acc[t], al, bh, acc[t]);
                }
            }
            // epilogue: C frag rows gid, gid+8; cols 2*tig, 2*tig+1
            #pragma unroll
            for (int t = 0; t < 4; t++) {
                int col = nb0 + t * 8 + 2 * tig;
                *(float2*)&S[(mb + gid)     * P + col] = make_float2(acc[t][0], acc[t][1]);
                *(float2*)&S[(mb + gid + 8) * P + col] = make_float2(acc[t][2], acc[t][3]);
            }
        }
        __syncthreads();

        // ============ softmax rows of S -> Ahi (in place) + Alo ============
        #pragma unroll
        for (int rr = 0; rr < 8; rr++) {
            int row = warp * 8 + rr;
            float v0 = S[row * P + lane];
            float v1 = S[row * P + lane + 32];
            float m = fmaxf(v0, v1);
            #pragma unroll
            for (int o = 16; o > 0; o >>= 1)
                m = fmaxf(m, __shfl_xor_sync(0xffffffffu, m, o));
            float e0 = __expf(v0 - m);
            float e1 = __expf(v1 - m);
            float sm = e0 + e1;
            #pragma unroll
            for (int o = 16; o > 0; o >>= 1)
                sm += __shfl_xor_sync(0xffffffffu, sm, o);
            float inv = __fdividef(1.0f, sm);
            float a0 = e0 * inv, a1 = e1 * inv;
            float h0 = tf32r(a0), h1 = tf32r(a1);
            S[row * P + lane]        = h0;
            S[row * P + lane + 32]   = h1;
            Alo[row * P + lane]      = tf32r(a0 - h0);
            Alo[row * P + lane + 32] = tf32r(a1 - h1);
        }
        __syncthreads();

        // ============ GEMM2: Xnew = A X (3xTF32) ============
        {
            float acc[4][4];
            #pragma unroll
            for (int t = 0; t < 4; t++)
                #pragma unroll
                for (int i = 0; i < 4; i++) acc[t][i] = 0.0f;

            #pragma unroll
            for (int k = 0; k < NDIM; k += 8) {      // k = inner (j) dim
                uint32_t ah[4], al[4];
                load_a(S,   ah, mb, k, gid, tig);    // Ahi
                load_a(Alo, al, mb, k, gid, tig);
                #pragma unroll
                for (int t = 0; t < 4; t++) {
                    int nb = nb0 + t * 8;
                    // B = X: B[k][n] = X[k][n]; b0:(k=tig,n=gid) b1:(k=tig+4)
                    uint32_t bh[2], bl[2];
                    bh[0] = __float_as_uint(Xhi[(k + tig)     * P + nb + gid]);
                    bh[1] = __float_as_uint(Xhi[(k + tig + 4) * P + nb + gid]);
                    bl[0] = __float_as_uint(Xlo[(k + tig)     * P + nb + gid]);
                    bl[1] = __float_as_uint(Xlo[(k + tig + 4) * P + nb + gid]);
                    mma_tf32(acc[t], ah, bh, acc[t]);
                    mma_tf32(acc[t], ah, bl, acc[t]);
                    mma_tf32(acc[t], al, bh, acc[t]);
                }
            }
            __syncthreads();   // everyone done reading old Xhi/Xlo

            // epilogue: split result back into Xhi/Xlo (hi+lo == X to 2^-23)
            #pragma unroll
            for (int t = 0; t < 4; t++) {
                int col = nb0 + t * 8 + 2 * tig;
                float h0 = tf32r(acc[t][0]), h1 = tf32r(acc[t][1]);
                float h2 = tf32r(acc[t][2]), h3 = tf32r(acc[t][3]);
                *(float2*)&Xhi[(mb + gid)     * P + col] = make_float2(h0, h1);
                *(float2*)&Xhi[(mb + gid + 8) * P + col] = make_float2(h2, h3);
                *(float2*)&Xlo[(mb + gid)     * P + col] =
                    make_float2(tf32r(acc[t][0] - h0), tf32r(acc[t][1] - h1));
                *(float2*)&Xlo[(mb + gid + 8) * P + col] =
                    make_float2(tf32r(acc[t][2] - h2), tf32r(acc[t][3] - h3));
            }
        }
        __syncthreads();
    }

    // ---- store: out = Xhi + Xlo (float4, coalesced) ----
    {
        float4* dst = (float4*)(out + base);
        #pragma unroll
        for (int i = 0; i < 4; i++) {
            int idx = tid + i * 256;
            int r = idx >> 4, c = (idx & 15) << 2;
            float4 h = *(float4*)&Xhi[r * P + c];
            float4 l = *(float4*)&Xlo[r * P + c];
            dst[idx] = make_float4(h.x + l.x, h.y + l.y, h.z + l.z, h.w + l.w);
        }
    }
}

extern "C" void kernel_launch(void* const* d_in, const int* in_sizes, int n_in,
                              void* d_out, int out_size) {
    const float* embeds = (const float*)d_in[0];
    float* out = (float*)d_out;
    int batches = in_sizes[0] / (NDIM * NDIM);   // 8192
    cudaFuncSetAttribute(autoint_tc_kernel,
                         cudaFuncAttributeMaxDynamicSharedMemorySize, SMEM_BYTES);
    autoint_tc_kernel<<<batches, 256, SMEM_BYTES>>>(embeds, out);
}

// round 3
// speedup vs baseline: 2.4913x; 2.1675x over previous
#include <cuda_runtime.h>
#include <cuda_fp16.h>
#include <cstdint>

// AutoInt [8192,64,64] fp32: 3 x { S = X X^T ; A = softmax(S) ; X = A X }.
// One CTA (128 thr, 4 warps) per batch. fp16 hi/lo 2-term split, 3-pass
// m16n8k16 HMMA. Warp tile m16 x n64: softmax + A fragments stay in
// registers (C-frag layout == A-frag layout). ldmatrix.x4 operand loads,
// double-buffered X -> one __syncthreads per layer.

#define NDIM   64
#define PH     72          // half pitch: 144B rows -> conflict-free ldmatrix
#define LAYERS 3

__device__ __forceinline__ uint32_t h2u(__half2 h) {
    return *reinterpret_cast<uint32_t*>(&h);
}
__device__ __forceinline__ uint32_t sptr(const void* p) {
    return (uint32_t)__cvta_generic_to_shared(p);
}
__device__ __forceinline__ void ldsm4(uint32_t addr, uint32_t r[4]) {
    asm volatile("ldmatrix.sync.aligned.m8n8.x4.shared.b16 {%0,%1,%2,%3}, [%4];"
                 : "=r"(r[0]), "=r"(r[1]), "=r"(r[2]), "=r"(r[3]) : "r"(addr));
}
__device__ __forceinline__ void ldsm4t(uint32_t addr, uint32_t r[4]) {
    asm volatile("ldmatrix.sync.aligned.m8n8.x4.trans.shared.b16 {%0,%1,%2,%3}, [%4];"
                 : "=r"(r[0]), "=r"(r[1]), "=r"(r[2]), "=r"(r[3]) : "r"(addr));
}
__device__ __forceinline__ void mma(float c[4], const uint32_t a[4],
                                    uint32_t b0, uint32_t b1) {
    asm volatile("mma.sync.aligned.m16n8k16.row.col.f32.f16.f16.f32 "
                 "{%0,%1,%2,%3}, {%4,%5,%6,%7}, {%8,%9}, {%0,%1,%2,%3};"
                 : "+f"(c[0]), "+f"(c[1]), "+f"(c[2]), "+f"(c[3])
                 : "r"(a[0]), "r"(a[1]), "r"(a[2]), "r"(a[3]), "r"(b0), "r"(b1));
}
// split (x,y) into packed fp16 hi pair + fp16 residual pair
__device__ __forceinline__ void split2(float x, float y, uint32_t& hi, uint32_t& lo) {
    __half2 h = __floats2half2_rn(x, y);
    float2 f = __half22float2(h);
    __half2 l = __floats2half2_rn(x - f.x, y - f.y);
    hi = h2u(h); lo = h2u(l);
}

__global__ __launch_bounds__(128)
void autoint_hmma_kernel(const float* __restrict__ in, float* __restrict__ out) {
    __shared__ __align__(16) __half Xh[2][NDIM * PH];
    __shared__ __align__(16) __half Xl[2][NDIM * PH];

    const int tid  = threadIdx.x;        // 128 threads, 4 warps
    const int lane = tid & 31;
    const int warp = tid >> 5;           // warp w owns rows 16w..16w+15
    const int gid  = lane >> 2;
    const int tig  = lane & 3;
    const int lrow = lane & 15;          // ldmatrix lane->row
    const int lcol = (lane >> 4) << 3;   // ldmatrix lane->col half (0/8)
    const size_t base = (size_t)blockIdx.x * (NDIM * NDIM);

    // ---- load gmem -> split into Xh/Xl buffer 0 ----
    {
        const float4* src = (const float4*)(in + base);
        #pragma unroll
        for (int i = 0; i < 8; i++) {
            int idx = tid + i * 128;                 // 1024 float4
            float4 v = src[idx];
            int r = idx >> 4, c = (idx & 15) << 2;
            uint32_t h01, l01, h23, l23;
            split2(v.x, v.y, h01, l01);
            split2(v.z, v.w, h23, l23);
            *(uint32_t*)&Xh[0][r * PH + c]     = h01;
            *(uint32_t*)&Xh[0][r * PH + c + 2] = h23;
            *(uint32_t*)&Xl[0][r * PH + c]     = l01;
            *(uint32_t*)&Xl[0][r * PH + c + 2] = l23;
        }
    }
    __syncthreads();

    int cur = 0;
    #pragma unroll
    for (int layer = 0; layer < LAYERS; layer++) {
        // ============ GEMM1: S = X X^T (warp rows 16w.., all 64 cols) ============
        float acc[8][4];
        #pragma unroll
        for (int nt = 0; nt < 8; nt++)
            #pragma unroll
            for (int i = 0; i < 4; i++) acc[nt][i] = 0.0f;

        #pragma unroll
        for (int ks = 0; ks < 4; ks++) {
            const int kk = ks * 16;
            uint32_t bh[4][4], bl[4][4];
            #pragma unroll
            for (int nb4 = 0; nb4 < 4; nb4++) {     // n-block of 16 rows of X
                ldsm4(sptr(&Xh[cur][(nb4 * 16 + lrow) * PH + kk + lcol]), bh[nb4]);
                ldsm4(sptr(&Xl[cur][(nb4 * 16 + lrow) * PH + kk + lcol]), bl[nb4]);
            }
            // A-frag (rows 16*warp..) == bh[warp]/bl[warp] (same ldmatrix result)
            #pragma unroll
            for (int nb4 = 0; nb4 < 4; nb4++)
                #pragma unroll
                for (int h = 0; h < 2; h++) {
                    int nt = nb4 * 2 + h;
                    mma(acc[nt], bh[warp], bh[nb4][h], bh[nb4][h + 2]);  // hi*hi
                    mma(acc[nt], bh[warp], bl[nb4][h], bl[nb4][h + 2]);  // hi*lo
                    mma(acc[nt], bl[warp], bh[nb4][h], bh[nb4][h + 2]);  // lo*hi
                }
        }

        // ============ softmax, fully register-resident ============
        // row r0 = 16*warp+gid in (c0,c1); row r1 = r0+8 in (c2,c3);
        // each row spread over 4 lanes (same gid) -> shfl xor 1,2.
        float m0 = -1e30f, m1 = -1e30f;
        #pragma unroll
        for (int nt = 0; nt < 8; nt++) {
            m0 = fmaxf(m0, fmaxf(acc[nt][0], acc[nt][1]));
            m1 = fmaxf(m1, fmaxf(acc[nt][2], acc[nt][3]));
        }
        m0 = fmaxf(m0, __shfl_xor_sync(0xffffffffu, m0, 1));
        m0 = fmaxf(m0, __shfl_xor_sync(0xffffffffu, m0, 2));
        m1 = fmaxf(m1, __shfl_xor_sync(0xffffffffu, m1, 1));
        m1 = fmaxf(m1, __shfl_xor_sync(0xffffffffu, m1, 2));
        float s0 = 0.0f, s1 = 0.0f;
        #pragma unroll
        for (int nt = 0; nt < 8; nt++) {
            acc[nt][0] = __expf(acc[nt][0] - m0);
            acc[nt][1] = __expf(acc[nt][1] - m0);
            acc[nt][2] = __expf(acc[nt][2] - m1);
            acc[nt][3] = __expf(acc[nt][3] - m1);
            s0 += acc[nt][0] + acc[nt][1];
            s1 += acc[nt][2] + acc[nt][3];
        }
        s0 += __shfl_xor_sync(0xffffffffu, s0, 1);
        s0 += __shfl_xor_sync(0xffffffffu, s0, 2);
        s1 += __shfl_xor_sync(0xffffffffu, s1, 1);
        s1 += __shfl_xor_sync(0xffffffffu, s1, 2);
        const float inv0 = __fdividef(1.0f, s0);
        const float inv1 = __fdividef(1.0f, s1);

        // A fragments direct from C layout (C m16n8 pair == A m16k16 frag)
        uint32_t AH[4][4], AL[4][4];
        #pragma unroll
        for (int ks = 0; ks < 4; ks++)
            #pragma unroll
            for (int j = 0; j < 2; j++) {
                int nt = ks * 2 + j;
                float v0 = acc[nt][0] * inv0, v1 = acc[nt][1] * inv0;
                float v2 = acc[nt][2] * inv1, v3 = acc[nt][3] * inv1;
                split2(v0, v1, AH[ks][2 * j],     AL[ks][2 * j]);      // row gid
                split2(v2, v3, AH[ks][2 * j + 1], AL[ks][2 * j + 1]);  // row gid+8
            }

        // ============ GEMM2: Xnew(rows 16w..) = A X ============
        float acc2[8][4];
        #pragma unroll
        for (int nt = 0; nt < 8; nt++)
            #pragma unroll
            for (int i = 0; i < 4; i++) acc2[nt][i] = 0.0f;

        #pragma unroll
        for (int ks = 0; ks < 4; ks++) {
            const int kk = ks * 16;
            #pragma unroll
            for (int nb4 = 0; nb4 < 4; nb4++) {
                uint32_t th[4], tl[4];
                ldsm4t(sptr(&Xh[cur][(kk + lrow) * PH + nb4 * 16 + lcol]), th);
                ldsm4t(sptr(&Xl[cur][(kk + lrow) * PH + nb4 * 16 + lcol]), tl);
                int nt = nb4 * 2;
                mma(acc2[nt], AH[ks], th[0], th[1]);
                mma(acc2[nt], AH[ks], tl[0], tl[1]);
                mma(acc2[nt], AL[ks], th[0], th[1]);
                mma(acc2[nt + 1], AH[ks], th[2], th[3]);
                mma(acc2[nt + 1], AH[ks], tl[2], tl[3]);
                mma(acc2[nt + 1], AL[ks], th[2], th[3]);
            }
        }

        const int r0 = warp * 16 + gid, r1 = r0 + 8;
        if (layer < LAYERS - 1) {
            const int nxt = cur ^ 1;   // writes go to the other buffer: no hazard
            #pragma unroll
            for (int nt = 0; nt < 8; nt++) {
                int col = nt * 8 + 2 * tig;
                uint32_t h01, l01, h23, l23;
                split2(acc2[nt][0], acc2[nt][1], h01, l01);
                split2(acc2[nt][2], acc2[nt][3], h23, l23);
                *(uint32_t*)&Xh[nxt][r0 * PH + col] = h01;
                *(uint32_t*)&Xl[nxt][r0 * PH + col] = l01;
                *(uint32_t*)&Xh[nxt][r1 * PH + col] = h23;
                *(uint32_t*)&Xl[nxt][r1 * PH + col] = l23;
            }
            __syncthreads();
            cur = nxt;
        } else {
            // final layer: write fp32 accumulators straight to gmem
            #pragma unroll
            for (int nt = 0; nt < 8; nt++) {
                int col = nt * 8 + 2 * tig;
                *(float2*)&out[base + r0 * NDIM + col] =
                    make_float2(acc2[nt][0], acc2[nt][1]);
                *(float2*)&out[base + r1 * NDIM + col] =
                    make_float2(acc2[nt][2], acc2[nt][3]);
            }
        }
    }
}

extern "C" void kernel_launch(void* const* d_in, const int* in_sizes, int n_in,
                              void* d_out, int out_size) {
    const float* embeds = (const float*)d_in[0];
    float* out = (float*)d_out;
    int batches = in_sizes[0] / (NDIM * NDIM);   // 8192
    autoint_hmma_kernel<<<batches, 128>>>(embeds, out);
}

// round 6
// speedup vs baseline: 2.8044x; 1.1257x over previous
#include <cuda_runtime.h>
#include <cuda_fp16.h>
#include <cstdint>

// AutoInt [8192,64,64] fp32: 3 x { S = X X^T ; A = softmax(S) ; X = A X }.
// One CTA (64 thr, 2 warps) per batch; warp tile m32 x n64. fp16 hi/lo
// 2-term split, 3-pass m16n8k16 HMMA. Softmax + A fragments fully
// register-resident. ldmatrix.x4 operand loads; double-buffered X.
// Hardened vs rounds 4/5 container failures: layer loop NOT unrolled
// (small code body, fast ptxas) and no forced min-blocks (no spill pressure).

#define NDIM   64
#define PH     72          // half pitch: 144B rows -> conflict-free ldmatrix
#define LAYERS 3

__device__ __forceinline__ uint32_t h2u(__half2 h) {
    return *reinterpret_cast<uint32_t*>(&h);
}
__device__ __forceinline__ uint32_t sptr(const void* p) {
    return (uint32_t)__cvta_generic_to_shared(p);
}
__device__ __forceinline__ void ldsm4(uint32_t addr, uint32_t r[4]) {
    asm volatile("ldmatrix.sync.aligned.m8n8.x4.shared.b16 {%0,%1,%2,%3}, [%4];"
                 : "=r"(r[0]), "=r"(r[1]), "=r"(r[2]), "=r"(r[3]) : "r"(addr));
}
__device__ __forceinline__ void ldsm4t(uint32_t addr, uint32_t r[4]) {
    asm volatile("ldmatrix.sync.aligned.m8n8.x4.trans.shared.b16 {%0,%1,%2,%3}, [%4];"
                 : "=r"(r[0]), "=r"(r[1]), "=r"(r[2]), "=r"(r[3]) : "r"(addr));
}
__device__ __forceinline__ void mma(float c[4], const uint32_t a[4],
                                    uint32_t b0, uint32_t b1) {
    asm volatile("mma.sync.aligned.m16n8k16.row.col.f32.f16.f16.f32 "
                 "{%0,%1,%2,%3}, {%4,%5,%6,%7}, {%8,%9}, {%0,%1,%2,%3};"
                 : "+f"(c[0]), "+f"(c[1]), "+f"(c[2]), "+f"(c[3])
                 : "r"(a[0]), "r"(a[1]), "r"(a[2]), "r"(a[3]), "r"(b0), "r"(b1));
}
__device__ __forceinline__ void split2(float x, float y, uint32_t& hi, uint32_t& lo) {
    __half2 h = __floats2half2_rn(x, y);
    float2 f = __half22float2(h);
    __half2 l = __floats2half2_rn(x - f.x, y - f.y);
    hi = h2u(h); lo = h2u(l);
}

__global__ __launch_bounds__(64)
void autoint_hmma2_kernel(const float* __restrict__ in, float* __restrict__ out) {
    __shared__ __align__(16) __half Xh[2][NDIM * PH];
    __shared__ __align__(16) __half Xl[2][NDIM * PH];

    const int tid  = threadIdx.x;        // 64 threads, 2 warps
    const int lane = tid & 31;
    const int warp = tid >> 5;           // warp w owns rows 32w..32w+31
    const int gid  = lane >> 2;
    const int tig  = lane & 3;
    const int lrow = lane & 15;          // ldmatrix lane->row
    const int lcol = (lane >> 4) << 3;   // ldmatrix lane->col half (0/8)
    const size_t base = (size_t)blockIdx.x * (NDIM * NDIM);

    // ---- load gmem -> split into Xh/Xl buffer 0 ----
    {
        const float4* src = (const float4*)(in + base);
        #pragma unroll
        for (int i = 0; i < 16; i++) {
            int idx = tid + i * 64;                  // 1024 float4
            float4 v = src[idx];
            int r = idx >> 4, c = (idx & 15) << 2;
            uint32_t h01, l01, h23, l23;
            split2(v.x, v.y, h01, l01);
            split2(v.z, v.w, h23, l23);
            *(uint32_t*)&Xh[0][r * PH + c]     = h01;
            *(uint32_t*)&Xh[0][r * PH + c + 2] = h23;
            *(uint32_t*)&Xl[0][r * PH + c]     = l01;
            *(uint32_t*)&Xl[0][r * PH + c + 2] = l23;
        }
    }
    __syncthreads();

    int cur = 0;
    #pragma unroll 1
    for (int layer = 0; layer < LAYERS; layer++) {
        // ===== GEMM1: S rows 32w..32w+31, all 64 cols (3-pass) =====
        float acc[2][8][4];
        #pragma unroll
        for (int mh = 0; mh < 2; mh++)
            #pragma unroll
            for (int nt = 0; nt < 8; nt++)
                #pragma unroll
                for (int i = 0; i < 4; i++) acc[mh][nt][i] = 0.0f;

        #pragma unroll
        for (int ks = 0; ks < 4; ks++) {
            const int kk = ks * 16;
            uint32_t bh[4][4], bl[4][4];
            #pragma unroll
            for (int nb4 = 0; nb4 < 4; nb4++) {
                ldsm4(sptr(&Xh[cur][(nb4 * 16 + lrow) * PH + kk + lcol]), bh[nb4]);
                ldsm4(sptr(&Xl[cur][(nb4 * 16 + lrow) * PH + kk + lcol]), bl[nb4]);
            }
            // A-frags for m-half mh are bh/bl[2*warp+mh] (same ldmatrix result)
            #pragma unroll
            for (int mh = 0; mh < 2; mh++) {
                const int aw = 2 * warp + mh;
                #pragma unroll
                for (int nb4 = 0; nb4 < 4; nb4++)
                    #pragma unroll
                    for (int h = 0; h < 2; h++) {
                        int nt = nb4 * 2 + h;
                        mma(acc[mh][nt], bh[aw], bh[nb4][h], bh[nb4][h + 2]);
                        mma(acc[mh][nt], bh[aw], bl[nb4][h], bl[nb4][h + 2]);
                        mma(acc[mh][nt], bl[aw], bh[nb4][h], bh[nb4][h + 2]);
                    }
            }
        }

        // ===== softmax (register-resident) + A-frag build =====
        uint32_t AH[2][4][4], AL[2][4][4];
        #pragma unroll
        for (int mh = 0; mh < 2; mh++) {
            float m0 = -1e30f, m1 = -1e30f;
            #pragma unroll
            for (int nt = 0; nt < 8; nt++) {
                m0 = fmaxf(m0, fmaxf(acc[mh][nt][0], acc[mh][nt][1]));
                m1 = fmaxf(m1, fmaxf(acc[mh][nt][2], acc[mh][nt][3]));
            }
            m0 = fmaxf(m0, __shfl_xor_sync(0xffffffffu, m0, 1));
            m0 = fmaxf(m0, __shfl_xor_sync(0xffffffffu, m0, 2));
            m1 = fmaxf(m1, __shfl_xor_sync(0xffffffffu, m1, 1));
            m1 = fmaxf(m1, __shfl_xor_sync(0xffffffffu, m1, 2));
            float s0 = 0.0f, s1 = 0.0f;
            #pragma unroll
            for (int nt = 0; nt < 8; nt++) {
                acc[mh][nt][0] = __expf(acc[mh][nt][0] - m0);
                acc[mh][nt][1] = __expf(acc[mh][nt][1] - m0);
                acc[mh][nt][2] = __expf(acc[mh][nt][2] - m1);
                acc[mh][nt][3] = __expf(acc[mh][nt][3] - m1);
                s0 += acc[mh][nt][0] + acc[mh][nt][1];
                s1 += acc[mh][nt][2] + acc[mh][nt][3];
            }
            s0 += __shfl_xor_sync(0xffffffffu, s0, 1);
            s0 += __shfl_xor_sync(0xffffffffu, s0, 2);
            s1 += __shfl_xor_sync(0xffffffffu, s1, 1);
            s1 += __shfl_xor_sync(0xffffffffu, s1, 2);
            const float inv0 = __fdividef(1.0f, s0);
            const float inv1 = __fdividef(1.0f, s1);
            // C-frag pair (nt=2ks, 2ks+1) == A m16k16 frag for k-chunk ks
            #pragma unroll
            for (int ks = 0; ks < 4; ks++)
                #pragma unroll
                for (int j = 0; j < 2; j++) {
                    int nt = ks * 2 + j;
                    split2(acc[mh][nt][0] * inv0, acc[mh][nt][1] * inv0,
                           AH[mh][ks][2 * j], AL[mh][ks][2 * j]);
                    split2(acc[mh][nt][2] * inv1, acc[mh][nt][3] * inv1,
                           AH[mh][ks][2 * j + 1], AL[mh][ks][2 * j + 1]);
                }
        }

        // ===== GEMM2: Xnew rows 32w..32w+31 = A X (3-pass) =====
        float acc2[2][8][4];
        #pragma unroll
        for (int mh = 0; mh < 2; mh++)
            #pragma unroll
            for (int nt = 0; nt < 8; nt++)
                #pragma unroll
                for (int i = 0; i < 4; i++) acc2[mh][nt][i] = 0.0f;

        #pragma unroll
        for (int ks = 0; ks < 4; ks++) {
            const int kk = ks * 16;
            #pragma unroll
            for (int nb4 = 0; nb4 < 4; nb4++) {
                uint32_t th[4], tl[4];
                ldsm4t(sptr(&Xh[cur][(kk + lrow) * PH + nb4 * 16 + lcol]), th);
                ldsm4t(sptr(&Xl[cur][(kk + lrow) * PH + nb4 * 16 + lcol]), tl);
                const int nt = nb4 * 2;
                #pragma unroll
                for (int mh = 0; mh < 2; mh++) {   // B loads amortized over 2 mh
                    mma(acc2[mh][nt], AH[mh][ks], th[0], th[1]);
                    mma(acc2[mh][nt], AH[mh][ks], tl[0], tl[1]);
                    mma(acc2[mh][nt], AL[mh][ks], th[0], th[1]);
                    mma(acc2[mh][nt + 1], AH[mh][ks], th[2], th[3]);
                    mma(acc2[mh][nt + 1], AH[mh][ks], tl[2], tl[3]);
                    mma(acc2[mh][nt + 1], AL[mh][ks], th[2], th[3]);
                }
            }
        }

        if (layer < LAYERS - 1) {
            const int nxt = cur ^ 1;   // other buffer: no WAR hazard
            #pragma unroll
            for (int mh = 0; mh < 2; mh++) {
                const int r0 = warp * 32 + mh * 16 + gid, r1 = r0 + 8;
                #pragma unroll
                for (int nt = 0; nt < 8; nt++) {
                    int col = nt * 8 + 2 * tig;
                    uint32_t h01, l01, h23, l23;
                    split2(acc2[mh][nt][0], acc2[mh][nt][1], h01, l01);
                    split2(acc2[mh][nt][2], acc2[mh][nt][3], h23, l23);
                    *(uint32_t*)&Xh[nxt][r0 * PH + col] = h01;
                    *(uint32_t*)&Xl[nxt][r0 * PH + col] = l01;
                    *(uint32_t*)&Xh[nxt][r1 * PH + col] = h23;
                    *(uint32_t*)&Xl[nxt][r1 * PH + col] = l23;
                }
            }
            __syncthreads();
            cur = nxt;
        } else {
            // final layer: fp32 accumulators straight to gmem
            #pragma unroll
            for (int mh = 0; mh < 2; mh++) {
                const int r0 = warp * 32 + mh * 16 + gid, r1 = r0 + 8;
                #pragma unroll
                for (int nt = 0; nt < 8; nt++) {
                    int col = nt * 8 + 2 * tig;
                    *(float2*)&out[base + r0 * NDIM + col] =
                        make_float2(acc2[mh][nt][0], acc2[mh][nt][1]);
                    *(float2*)&out[base + r1 * NDIM + col] =
                        make_float2(acc2[mh][nt][2], acc2[mh][nt][3]);
                }
            }
        }
    }
}

extern "C" void kernel_launch(void* const* d_in, const int* in_sizes, int n_in,
                              void* d_out, int out_size) {
    const float* embeds = (const float*)d_in[0];
    float* out = (float*)d_out;
    int batches = in_sizes[0] / (NDIM * NDIM);   // 8192
    autoint_hmma2_kernel<<<batches, 64>>>(embeds, out);
}